// round 2
// baseline (speedup 1.0000x reference)
#include <cuda_runtime.h>
#include <cuda_bf16.h>
#include <math.h>

#define NMAX 100000
#define EMAX 400000
#define DHD  128
#define DIN  32
__device__ __constant__ float EPSC = 1e-5f;

// ------------- device scratch (no runtime allocation allowed) ---------------
__device__ float  g_H[(size_t)NMAX * DHD];     // 51.2 MB
__device__ float  g_A[(size_t)NMAX * DHD];     // 51.2 MB
__device__ float  g_dinv[NMAX];
__device__ int    g_cnt[NMAX];
__device__ int    g_fill[NMAX];
__device__ int    g_incl[NMAX];
__device__ int    g_rowptr[NMAX + 1];
__device__ int    g_col[EMAX];
__device__ float  g_val[EMAX];
__device__ float  g_y[NMAX];
__device__ float  g_gy[NMAX];
__device__ double g_sum[DHD];
__device__ double g_sq[DHD];
__device__ float  g_scale[DHD];
__device__ float  g_mean[DHD];
__device__ int    g_is32;
__device__ int    g_bsum[128];
__device__ int    g_tops[128];

// --------------------------- small helpers ---------------------------------
__device__ __forceinline__ void load_edge(const void* ei, int E, int e, int& s, int& d) {
    if (g_is32) {
        const int* p = (const int*)ei;
        s = p[e]; d = p[E + e];
    } else {
        const long long* p = (const long long*)ei;
        s = (int)p[e]; d = (int)p[E + e];
    }
}

// ------------------------------- kernels ------------------------------------
__global__ void k_zero_init(int n) {
    int i = blockIdx.x * blockDim.x + threadIdx.x;
    if (i < n) { g_cnt[i] = 0; g_fill[i] = 0; }
    if (i == 0) g_is32 = 0;
}

// Detect int32 vs int64 edge_index: if int64, every odd 32-bit word of the
// first 4096 values is the (zero) high half of a value < 1e5.
__global__ void k_detect(const void* ei) {
    int idx = blockIdx.x * blockDim.x + threadIdx.x;
    if (idx < 4096) {
        int w = ((const int*)ei)[2 * idx + 1];
        if (w != 0) g_is32 = 1;
    }
}

__global__ void k_count(const void* ei, int E) {
    int e = blockIdx.x * blockDim.x + threadIdx.x;
    if (e < E) {
        int s, d; load_edge(ei, E, e, s, d);
        atomicAdd(&g_cnt[d], 1);
    }
}

__global__ void k_dinv(int n) {
    int i = blockIdx.x * blockDim.x + threadIdx.x;
    if (i < n) g_dinv[i] = rsqrtf((float)(g_cnt[i] + 1));  // +1 self-loop
}

// ---- 3-kernel scan of g_cnt -> g_rowptr (exclusive) ----
__global__ void k_scan_local(int n, int nblocks) {
    __shared__ int sh[1024];
    int t = threadIdx.x;
    int i = blockIdx.x * 1024 + t;
    int v = (i < n) ? g_cnt[i] : 0;
    sh[t] = v;
    __syncthreads();
    for (int off = 1; off < 1024; off <<= 1) {
        int add = (t >= off) ? sh[t - off] : 0;
        __syncthreads();
        sh[t] += add;
        __syncthreads();
    }
    if (i < n) g_incl[i] = sh[t];
    if (t == 1023) g_bsum[blockIdx.x] = sh[1023];
}

__global__ void k_scan_tops(int nblocks) {
    __shared__ int sh[128];
    int t = threadIdx.x;
    int orig = (t < nblocks) ? g_bsum[t] : 0;
    sh[t] = orig;
    __syncthreads();
    for (int off = 1; off < 128; off <<= 1) {
        int add = (t >= off) ? sh[t - off] : 0;
        __syncthreads();
        sh[t] += add;
        __syncthreads();
    }
    g_tops[t] = sh[t] - orig;   // exclusive prefix of block sums
}

__global__ void k_scan_final(int n) {
    int i = blockIdx.x * blockDim.x + threadIdx.x;
    if (i < n) g_rowptr[i + 1] = g_incl[i] + g_tops[i >> 10];
    if (i == 0) g_rowptr[0] = 0;
}

__global__ void k_fill(const void* ei, int E) {
    int e = blockIdx.x * blockDim.x + threadIdx.x;
    if (e < E) {
        int s, d; load_edge(ei, E, e, s, d);
        int p = g_rowptr[d] + atomicAdd(&g_fill[d], 1);
        g_col[p] = s;
        g_val[p] = g_dinv[s] * g_dinv[d];
    }
}

// ---- gathers (CSR by dst; self-loop weight = dinv^2) ----
__global__ void k_gather32(const float* __restrict__ x, float* __restrict__ out, int n) {
    int node = blockIdx.x * 4 + (threadIdx.x >> 5);
    int c = threadIdx.x & 31;
    if (node >= n) return;
    float di = g_dinv[node];
    float acc = x[(size_t)node * DIN + c] * di * di;
    int e0 = g_rowptr[node], e1 = g_rowptr[node + 1];
    for (int e = e0; e < e1; e++) {
        acc += x[(size_t)g_col[e] * DIN + c] * g_val[e];
    }
    out[(size_t)node * DIN + c] = acc;
}

__global__ void __launch_bounds__(128) k_gather128(const float* __restrict__ h,
                                                   float* __restrict__ out, int n) {
    int node = blockIdx.x;
    int c = threadIdx.x;
    float di = g_dinv[node];
    float acc = h[(size_t)node * DHD + c] * di * di;
    int e0 = g_rowptr[node], e1 = g_rowptr[node + 1];
    for (int e = e0; e < e1; e++) {
        acc += h[(size_t)g_col[e] * DHD + c] * g_val[e];
    }
    out[(size_t)node * DHD + c] = acc;
}

__global__ void k_gather1(const float* __restrict__ y, float* __restrict__ out, int n) {
    int i = blockIdx.x * blockDim.x + threadIdx.x;
    if (i >= n) return;
    float di = g_dinv[i];
    float acc = y[i] * di * di;
    int e0 = g_rowptr[i], e1 = g_rowptr[i + 1];
    for (int e = e0; e < e1; e++) acc += y[g_col[e]] * g_val[e];
    out[i] = acc;
}

// ---- SGEMM: Y[n x 128] = X[n x K] @ W[K x 128] ----
#define BM 64
#define BN 128
#define BK 32
#define TM 8
#define TN 4
__global__ void __launch_bounds__(256) k_gemm(const float* __restrict__ X,
                                              const float* __restrict__ W,
                                              float* __restrict__ Y, int n, int K) {
    __shared__ float Xs[BM][BK];
    __shared__ float Ws[BK][BN];
    int tid = threadIdx.x;
    int tx = tid & 31;   // col group (4 cols)
    int ty = tid >> 5;   // row group (8 rows)
    int r0 = blockIdx.x * BM;
    float acc[TM][TN];
#pragma unroll
    for (int i = 0; i < TM; i++)
#pragma unroll
        for (int j = 0; j < TN; j++) acc[i][j] = 0.f;

    for (int kc = 0; kc < K; kc += BK) {
        for (int idx = tid; idx < BM * BK; idx += 256) {
            int r = idx >> 5, k = idx & 31;
            int gr = r0 + r;
            Xs[r][k] = (gr < n) ? X[(size_t)gr * K + kc + k] : 0.f;
        }
        for (int idx = tid; idx < BK * BN; idx += 256) {
            int k = idx >> 7, c = idx & 127;
            Ws[k][c] = W[(size_t)(kc + k) * BN + c];
        }
        __syncthreads();
#pragma unroll
        for (int k = 0; k < BK; k++) {
            float4 b4 = ((const float4*)Ws[k])[tx];
            float b[TN] = {b4.x, b4.y, b4.z, b4.w};
#pragma unroll
            for (int i = 0; i < TM; i++) {
                float a = Xs[ty * TM + i][k];
#pragma unroll
                for (int j = 0; j < TN; j++) acc[i][j] = fmaf(a, b[j], acc[i][j]);
            }
        }
        __syncthreads();
    }
#pragma unroll
    for (int i = 0; i < TM; i++) {
        int gr = r0 + ty * TM + i;
        if (gr < n) {
            float4 v = make_float4(acc[i][0], acc[i][1], acc[i][2], acc[i][3]);
            ((float4*)(Y + (size_t)gr * BN))[tx] = v;
        }
    }
}

// ---- GEMV: y[n] = H[n x 128] @ w[128] ----
__global__ void k_gemv(const float* __restrict__ H, const float* __restrict__ W3,
                       float* __restrict__ y, int n) {
    __shared__ float w[DHD];
    if (threadIdx.x < DHD) w[threadIdx.x] = W3[threadIdx.x];
    __syncthreads();
    int warp = threadIdx.x >> 5, lane = threadIdx.x & 31;
    int row = blockIdx.x * 8 + warp;
    if (row >= n) return;
    const float* h = H + (size_t)row * DHD;
    float s = 0.f;
#pragma unroll
    for (int k = 0; k < 4; k++) s = fmaf(h[lane + 32 * k], w[lane + 32 * k], s);
#pragma unroll
    for (int o = 16; o; o >>= 1) s += __shfl_xor_sync(0xFFFFFFFFu, s, o);
    if (lane == 0) y[row] = s;
}

// ---- stats ----
__global__ void k_zero_stats() {
    int c = threadIdx.x;
    g_sum[c] = 0.0; g_sq[c] = 0.0;
}

__global__ void __launch_bounds__(128) k_stats128(const float* __restrict__ A, int n) {
    int c = threadIdx.x;
    double s = 0.0, ss = 0.0;
    for (int r = blockIdx.x; r < n; r += gridDim.x) {
        float v = A[(size_t)r * DHD + c];
        s += v;
        ss += (double)v * (double)v;
    }
    atomicAdd(&g_sum[c], s);
    atomicAdd(&g_sq[c], ss);
}

__global__ void k_stats1(const float* __restrict__ v, int n) {
    __shared__ double s1[256], s2[256];
    int t = threadIdx.x;
    double s = 0.0, ss = 0.0;
    for (int i = blockIdx.x * 256 + t; i < n; i += gridDim.x * 256) {
        float x = v[i];
        s += x; ss += (double)x * (double)x;
    }
    s1[t] = s; s2[t] = ss;
    __syncthreads();
    for (int o = 128; o; o >>= 1) {
        if (t < o) { s1[t] += s1[t + o]; s2[t] += s2[t + o]; }
        __syncthreads();
    }
    if (t == 0) { atomicAdd(&g_sum[0], s1[0]); atomicAdd(&g_sq[0], s2[0]); }
}

// bn∘inorm∘lnorm collapses to (A - m_c)*scale_c + lb_c; lnorm global mean is 0.
__global__ void k_consts(const float* __restrict__ g, const float* __restrict__ lw,
                         int C, int n) {
    __shared__ float red[128];
    int c = threadIdx.x;
    float alpha = 0.f, v = 0.f, m = 0.f;
    if (c < C) {
        double md = g_sum[c] / (double)n;
        double vd = g_sq[c] / (double)n - md * md;
        if (vd < 0.0) vd = 0.0;
        m = (float)md; v = (float)vd;
        float r1 = rsqrtf(v + EPSC);
        float gv = g[c];
        float var1 = gv * gv * v * r1 * r1;       // var of BN output
        alpha = gv * r1 * rsqrtf(var1 + EPSC);    // inorm(bn(.)) slope
        red[c] = alpha * alpha * v;               // contribution to lnorm var
    } else {
        red[c] = 0.f;
    }
    __syncthreads();
    for (int o = 64; o; o >>= 1) {
        if (c < o) red[c] += red[c + o];
        __syncthreads();
    }
    float v2 = red[0] / (float)C;
    if (c < C) {
        g_scale[c] = alpha * rsqrtf(v2 + EPSC) * lw[c];
        g_mean[c] = m;
    }
}

__global__ void k_normalize(const float* __restrict__ A, float* __restrict__ out,
                            const float* __restrict__ lb, int total, int relu) {
    int idx = blockIdx.x * blockDim.x + threadIdx.x;
    if (idx >= total) return;
    int c = idx & (DHD - 1);
    float v = (A[idx] - g_mean[c]) * g_scale[c] + lb[c];
    if (relu) v = fmaxf(v, 0.f);
    out[idx] = v;
}

__global__ void k_final(const float* __restrict__ gy, float* __restrict__ out,
                        const float* __restrict__ lb3, int n) {
    int i = blockIdx.x * blockDim.x + threadIdx.x;
    if (i < n) out[i] = (gy[i] - g_mean[0]) * g_scale[0] + lb3[0];
}

// ------------------------------ launch --------------------------------------
extern "C" void kernel_launch(void* const* d_in, const int* in_sizes, int n_in,
                              void* d_out, int out_size) {
    const float* x  = (const float*)d_in[0];
    const void*  ei = d_in[1];
    const float* W1 = (const float*)d_in[2];
    const float* g1 = (const float*)d_in[4];
    const float* lw1 = (const float*)d_in[6];
    const float* lb1 = (const float*)d_in[7];
    const float* W2 = (const float*)d_in[8];
    const float* g2 = (const float*)d_in[10];
    const float* lw2 = (const float*)d_in[12];
    const float* lb2 = (const float*)d_in[13];
    const float* W3 = (const float*)d_in[14];
    const float* g3 = (const float*)d_in[16];
    const float* lw3 = (const float*)d_in[18];
    const float* lb3 = (const float*)d_in[19];

    int n = in_sizes[0] / DIN;   // 100000
    int E = in_sizes[1] / 2;     // 400000
    int nb1024 = (n + 1023) / 1024;

    float* Hb; float* Ab; float* yb; float* gyb;
    cudaGetSymbolAddress((void**)&Hb,  g_H);
    cudaGetSymbolAddress((void**)&Ab,  g_A);
    cudaGetSymbolAddress((void**)&yb,  g_y);
    cudaGetSymbolAddress((void**)&gyb, g_gy);

    // ---- graph preprocessing: degrees, dinv, CSR(dst) with edge weights ----
    k_zero_init<<<(n + 255) / 256, 256>>>(n);
    k_detect<<<16, 256>>>(ei);
    k_count<<<(E + 255) / 256, 256>>>(ei, E);
    k_dinv<<<(n + 255) / 256, 256>>>(n);
    k_scan_local<<<nb1024, 1024>>>(n, nb1024);
    k_scan_tops<<<1, 128>>>(nb1024);
    k_scan_final<<<(n + 255) / 256, 256>>>(n);
    k_fill<<<(E + 255) / 256, 256>>>(ei, E);

    // ---- layer 1: agg(x) @ W1, fused norm stack, relu ----
    k_gather32<<<(n + 3) / 4, 128>>>(x, Ab, n);
    k_gemm<<<(n + BM - 1) / BM, 256>>>(Ab, W1, Hb, n, DIN);
    k_zero_stats<<<1, 128>>>();
    k_stats128<<<512, 128>>>(Hb, n);
    k_consts<<<1, 128>>>(g1, lw1, DHD, n);
    k_normalize<<<(n * DHD + 255) / 256, 256>>>(Hb, Ab, lb1, n * DHD, 1);

    // ---- layer 2: agg(h1) @ W2, fused norm stack, relu ----
    k_gather128<<<n, 128>>>(Ab, Hb, n);
    k_gemm<<<(n + BM - 1) / BM, 256>>>(Hb, W2, Ab, n, DHD);
    k_zero_stats<<<1, 128>>>();
    k_stats128<<<512, 128>>>(Ab, n);
    k_consts<<<1, 128>>>(g2, lw2, DHD, n);
    k_normalize<<<(n * DHD + 255) / 256, 256>>>(Ab, Hb, lb2, n * DHD, 1);

    // ---- layer 3: (h2 @ W3) then scalar aggregation, fused norm stack ----
    k_gemv<<<(n + 7) / 8, 256>>>(Hb, W3, yb, n);
    k_gather1<<<(n + 255) / 256, 256>>>(yb, gyb, n);
    k_zero_stats<<<1, 128>>>();
    k_stats1<<<256, 256>>>(gyb, n);
    k_consts<<<1, 128>>>(g3, lw3, 1, n);
    k_final<<<(n + 255) / 256, 256>>>(gyb, (float*)d_out, lb3, n);
}

// round 4
// speedup vs baseline: 1.4173x; 1.4173x over previous
#include <cuda_runtime.h>
#include <cuda_bf16.h>
#include <math.h>

#define NMAX 100000
#define EMAX 400000
#define DHD  128
#define DIN  32
__device__ __constant__ float EPSC = 1e-5f;

// ------------- device scratch (no runtime allocation allowed) ---------------
__device__ float  g_H[(size_t)NMAX * DHD];     // 51.2 MB
__device__ float  g_A[(size_t)NMAX * DHD];     // 51.2 MB
__device__ float  g_dinv[NMAX];
__device__ int    g_cnt[NMAX];
__device__ int    g_fill[NMAX];
__device__ int    g_incl[NMAX];
__device__ int    g_rowptr[NMAX + 1];
__device__ int    g_col[EMAX];
__device__ float  g_val[EMAX];
__device__ float  g_y[NMAX];
__device__ float  g_gy[NMAX];
__device__ double g_sum[DHD];
__device__ double g_sq[DHD];
__device__ float  g_scale[DHD];
__device__ float  g_beta[DHD];
__device__ int    g_is32;
__device__ int    g_bsum[128];
__device__ int    g_tops[128];

// --------------------------- f32x2 helpers ----------------------------------
__device__ __forceinline__ unsigned long long pk2(float lo, float hi) {
    unsigned long long r;
    asm("mov.b64 %0, {%1, %2};" : "=l"(r) : "f"(lo), "f"(hi));
    return r;
}
__device__ __forceinline__ void unpk2(unsigned long long v, float& lo, float& hi) {
    asm("mov.b64 {%0, %1}, %2;" : "=f"(lo), "=f"(hi) : "l"(v));
}
#define FMA2(c, a, b) asm("fma.rn.f32x2 %0, %1, %2, %0;" : "+l"(c) : "l"(a), "l"(b))

// --------------------------- small helpers ---------------------------------
__device__ __forceinline__ void load_edge(const void* ei, int E, int e, int& s, int& d) {
    if (g_is32) {
        const int* p = (const int*)ei;
        s = p[e]; d = p[E + e];
    } else {
        const long long* p = (const long long*)ei;
        s = (int)p[e]; d = (int)p[E + e];
    }
}

// ------------------------------- preprocessing ------------------------------
__global__ void k_zero_init(int n) {
    int i = blockIdx.x * blockDim.x + threadIdx.x;
    if (i < n) { g_cnt[i] = 0; g_fill[i] = 0; }
    if (i == 0) g_is32 = 0;
}

__global__ void k_detect(const void* ei) {
    int idx = blockIdx.x * blockDim.x + threadIdx.x;
    if (idx < 4096) {
        int w = ((const int*)ei)[2 * idx + 1];
        if (w != 0) g_is32 = 1;
    }
}

__global__ void k_count(const void* ei, int E) {
    int e = blockIdx.x * blockDim.x + threadIdx.x;
    if (e < E) {
        int s, d; load_edge(ei, E, e, s, d);
        atomicAdd(&g_cnt[d], 1);
    }
}

__global__ void k_dinv(int n) {
    int i = blockIdx.x * blockDim.x + threadIdx.x;
    if (i < n) g_dinv[i] = rsqrtf((float)(g_cnt[i] + 1));  // +1 self-loop
}

__global__ void k_scan_local(int n, int nblocks) {
    __shared__ int sh[1024];
    int t = threadIdx.x;
    int i = blockIdx.x * 1024 + t;
    int v = (i < n) ? g_cnt[i] : 0;
    sh[t] = v;
    __syncthreads();
    for (int off = 1; off < 1024; off <<= 1) {
        int add = (t >= off) ? sh[t - off] : 0;
        __syncthreads();
        sh[t] += add;
        __syncthreads();
    }
    if (i < n) g_incl[i] = sh[t];
    if (t == 1023) g_bsum[blockIdx.x] = sh[1023];
}

__global__ void k_scan_tops(int nblocks) {
    __shared__ int sh[128];
    int t = threadIdx.x;
    int orig = (t < nblocks) ? g_bsum[t] : 0;
    sh[t] = orig;
    __syncthreads();
    for (int off = 1; off < 128; off <<= 1) {
        int add = (t >= off) ? sh[t - off] : 0;
        __syncthreads();
        sh[t] += add;
        __syncthreads();
    }
    g_tops[t] = sh[t] - orig;
}

__global__ void k_scan_final(int n) {
    int i = blockIdx.x * blockDim.x + threadIdx.x;
    if (i < n) g_rowptr[i + 1] = g_incl[i] + g_tops[i >> 10];
    if (i == 0) g_rowptr[0] = 0;
}

__global__ void k_fill(const void* ei, int E) {
    int e = blockIdx.x * blockDim.x + threadIdx.x;
    if (e < E) {
        int s, d; load_edge(ei, E, e, s, d);
        int p = g_rowptr[d] + atomicAdd(&g_fill[d], 1);
        g_col[p] = s;
        g_val[p] = g_dinv[s] * g_dinv[d];
    }
}

// ---- gathers (CSR by dst; self-loop weight = dinv^2) ----
__global__ void k_gather32(const float* __restrict__ x, float* __restrict__ out, int n) {
    int node = blockIdx.x * 4 + (threadIdx.x >> 5);
    int c = threadIdx.x & 31;
    if (node >= n) return;
    float di = g_dinv[node];
    float acc = x[(size_t)node * DIN + c] * di * di;
    int e0 = g_rowptr[node], e1 = g_rowptr[node + 1];
    for (int e = e0; e < e1; e++) {
        acc += x[(size_t)g_col[e] * DIN + c] * g_val[e];
    }
    out[(size_t)node * DIN + c] = acc;
}

// gather over h with the norm-affine + relu applied at load time:
//   hn[c] = relu(h[c]*scale[c] + beta[c])
__device__ __forceinline__ float4 aff_relu4(float4 v, float4 s, float4 b) {
    float4 r;
    r.x = fmaxf(fmaf(v.x, s.x, b.x), 0.f);
    r.y = fmaxf(fmaf(v.y, s.y, b.y), 0.f);
    r.z = fmaxf(fmaf(v.z, s.z, b.z), 0.f);
    r.w = fmaxf(fmaf(v.w, s.w, b.w), 0.f);
    return r;
}

__global__ void __launch_bounds__(128) k_gather128n(const float* __restrict__ h,
                                                    float* __restrict__ out, int n) {
    int node = blockIdx.x * 4 + (threadIdx.x >> 5);
    int lane = threadIdx.x & 31;
    if (node >= n) return;
    float4 sc = ((const float4*)g_scale)[lane];
    float4 bt = ((const float4*)g_beta)[lane];
    float di = g_dinv[node];
    float w_self = di * di;
    float4 v = ((const float4*)(h + (size_t)node * DHD))[lane];
    float4 a = aff_relu4(v, sc, bt);
    float4 acc = make_float4(a.x * w_self, a.y * w_self, a.z * w_self, a.w * w_self);
    int e0 = g_rowptr[node], e1 = g_rowptr[node + 1];
    int e = e0;
    for (; e + 1 < e1; e += 2) {
        int c0 = g_col[e], c1 = g_col[e + 1];
        float w0 = g_val[e], w1 = g_val[e + 1];
        float4 x0 = ((const float4*)(h + (size_t)c0 * DHD))[lane];
        float4 x1 = ((const float4*)(h + (size_t)c1 * DHD))[lane];
        float4 n0 = aff_relu4(x0, sc, bt);
        float4 n1 = aff_relu4(x1, sc, bt);
        acc.x += n0.x * w0 + n1.x * w1;
        acc.y += n0.y * w0 + n1.y * w1;
        acc.z += n0.z * w0 + n1.z * w1;
        acc.w += n0.w * w0 + n1.w * w1;
    }
    if (e < e1) {
        int c0 = g_col[e]; float w0 = g_val[e];
        float4 x0 = ((const float4*)(h + (size_t)c0 * DHD))[lane];
        float4 n0 = aff_relu4(x0, sc, bt);
        acc.x += n0.x * w0; acc.y += n0.y * w0;
        acc.z += n0.z * w0; acc.w += n0.w * w0;
    }
    ((float4*)(out + (size_t)node * DHD))[lane] = acc;
}

__global__ void k_gather1(const float* __restrict__ y, float* __restrict__ out, int n) {
    int i = blockIdx.x * blockDim.x + threadIdx.x;
    if (i >= n) return;
    float di = g_dinv[i];
    float acc = y[i] * di * di;
    int e0 = g_rowptr[i], e1 = g_rowptr[i + 1];
    int e = e0;
    // 4-wide unroll: raise MLP so DRAM/L2 latency overlaps (577/MLP model)
    for (; e + 3 < e1; e += 4) {
        int c0 = g_col[e], c1 = g_col[e + 1], c2 = g_col[e + 2], c3 = g_col[e + 3];
        float y0 = y[c0], y1 = y[c1], y2 = y[c2], y3 = y[c3];
        acc += y0 * g_val[e] + y1 * g_val[e + 1] + y2 * g_val[e + 2] + y3 * g_val[e + 3];
    }
    for (; e < e1; e++) acc += y[g_col[e]] * g_val[e];
    out[i] = acc;
}

// ---- SGEMM with packed f32x2 FMA: Y[n x 128] = X[n x K] @ W[K x 128] -------
// Fused epilogue: per-channel sum / sumsq accumulated into g_sum / g_sq.
#define BM 128
#define BN 128
#define BK 16
__global__ void __launch_bounds__(256) k_gemm(const float* __restrict__ X,
                                              const float* __restrict__ W,
                                              float* __restrict__ Y, int n, int K) {
    __shared__ float Xs[BK][BM + 4];   // transposed X tile
    __shared__ float Ws[BK][BN];
    int tid = threadIdx.x;
    int tx = tid & 15, ty = tid >> 4;
    int r0 = blockIdx.x * BM;

    unsigned long long acc[4][8];      // [row-pair][col]
#pragma unroll
    for (int i = 0; i < 4; i++)
#pragma unroll
        for (int j = 0; j < 8; j++) acc[i][j] = 0ULL;

    for (int kc = 0; kc < K; kc += BK) {
#pragma unroll
        for (int l = 0; l < 2; l++) {
            int li = tid + l * 256;
            int r = li >> 2, k4 = (li & 3) * 4;
            float4 v = make_float4(0.f, 0.f, 0.f, 0.f);
            if (r0 + r < n) v = *(const float4*)(X + (size_t)(r0 + r) * K + kc + k4);
            Xs[k4 + 0][r] = v.x; Xs[k4 + 1][r] = v.y;
            Xs[k4 + 2][r] = v.z; Xs[k4 + 3][r] = v.w;
        }
#pragma unroll
        for (int l = 0; l < 2; l++) {
            int li = tid + l * 256;
            int k = li >> 5, c4 = (li & 31) * 4;
            *(float4*)&Ws[k][c4] = *(const float4*)(W + (size_t)(kc + k) * BN + c4);
        }
        __syncthreads();
#pragma unroll
        for (int k = 0; k < BK; k++) {
            float4 a0 = *(float4*)&Xs[k][ty * 8];
            float4 a1 = *(float4*)&Xs[k][ty * 8 + 4];
            float4 b0 = *(float4*)&Ws[k][tx * 8];
            float4 b1 = *(float4*)&Ws[k][tx * 8 + 4];
            unsigned long long ap[4];
            ap[0] = pk2(a0.x, a0.y); ap[1] = pk2(a0.z, a0.w);
            ap[2] = pk2(a1.x, a1.y); ap[3] = pk2(a1.z, a1.w);
            float bb[8] = {b0.x, b0.y, b0.z, b0.w, b1.x, b1.y, b1.z, b1.w};
#pragma unroll
            for (int j = 0; j < 8; j++) {
                unsigned long long bp = pk2(bb[j], bb[j]);
#pragma unroll
                for (int i = 0; i < 4; i++) FMA2(acc[i][j], ap[i], bp);
            }
        }
        __syncthreads();
    }

    // ---- write Y + per-channel stats ----
    float colsum[8], colsq[8];
#pragma unroll
    for (int j = 0; j < 8; j++) { colsum[j] = 0.f; colsq[j] = 0.f; }
#pragma unroll
    for (int i = 0; i < 4; i++) {
        float lo[8], hi[8];
#pragma unroll
        for (int j = 0; j < 8; j++) {
            unpk2(acc[i][j], lo[j], hi[j]);
            colsum[j] += lo[j] + hi[j];
            colsq[j] += lo[j] * lo[j] + hi[j] * hi[j];
        }
        int gr = r0 + ty * 8 + 2 * i;
        if (gr < n) {
            *(float4*)(Y + (size_t)gr * BN + tx * 8) = make_float4(lo[0], lo[1], lo[2], lo[3]);
            *(float4*)(Y + (size_t)gr * BN + tx * 8 + 4) = make_float4(lo[4], lo[5], lo[6], lo[7]);
        }
        if (gr + 1 < n) {
            *(float4*)(Y + (size_t)(gr + 1) * BN + tx * 8) = make_float4(hi[0], hi[1], hi[2], hi[3]);
            *(float4*)(Y + (size_t)(gr + 1) * BN + tx * 8 + 4) = make_float4(hi[4], hi[5], hi[6], hi[7]);
        }
    }
    __syncthreads();
    float* red = &Xs[0][0];   // reuse smem: need 16*128 floats
#pragma unroll
    for (int j = 0; j < 8; j++) red[ty * 128 + tx * 8 + j] = colsum[j];
    __syncthreads();
    if (tid < 128) {
        float s = 0.f;
#pragma unroll
        for (int t = 0; t < 16; t++) s += red[t * 128 + tid];
        atomicAdd(&g_sum[tid], (double)s);
    }
    __syncthreads();
#pragma unroll
    for (int j = 0; j < 8; j++) red[ty * 128 + tx * 8 + j] = colsq[j];
    __syncthreads();
    if (tid < 128) {
        float s = 0.f;
#pragma unroll
        for (int t = 0; t < 16; t++) s += red[t * 128 + tid];
        atomicAdd(&g_sq[tid], (double)s);
    }
}

// ---- GEMV with fused affine+relu on input: y = relu(H*s+b) @ w3 -----------
__global__ void __launch_bounds__(256) k_gemv(const float* __restrict__ H,
                                              const float* __restrict__ W3,
                                              float* __restrict__ y, int n) {
    __shared__ float w[DHD], sc[DHD], bt[DHD];
    if (threadIdx.x < DHD) {
        w[threadIdx.x] = W3[threadIdx.x];
        sc[threadIdx.x] = g_scale[threadIdx.x];
        bt[threadIdx.x] = g_beta[threadIdx.x];
    }
    __syncthreads();
    int warp = threadIdx.x >> 5, lane = threadIdx.x & 31;
    int row = blockIdx.x * 8 + warp;
    if (row >= n) return;
    const float* h = H + (size_t)row * DHD;
    float s = 0.f;
#pragma unroll
    for (int k = 0; k < 4; k++) {
        int c = lane + 32 * k;
        float v = fmaxf(fmaf(h[c], sc[c], bt[c]), 0.f);
        s = fmaf(v, w[c], s);
    }
#pragma unroll
    for (int o = 16; o; o >>= 1) s += __shfl_xor_sync(0xFFFFFFFFu, s, o);
    if (lane == 0) y[row] = s;
}

// ---- stats ----
__global__ void k_zero_stats() {
    int c = threadIdx.x;
    g_sum[c] = 0.0; g_sq[c] = 0.0;
}

__global__ void k_stats1(const float* __restrict__ v, int n) {
    __shared__ double s1[256], s2[256];
    int t = threadIdx.x;
    double s = 0.0, ss = 0.0;
    for (int i = blockIdx.x * 256 + t; i < n; i += gridDim.x * 256) {
        float x = v[i];
        s += x; ss += (double)x * (double)x;
    }
    s1[t] = s; s2[t] = ss;
    __syncthreads();
    for (int o = 128; o; o >>= 1) {
        if (t < o) { s1[t] += s1[t + o]; s2[t] += s2[t + o]; }
        __syncthreads();
    }
    if (t == 0) { atomicAdd(&g_sum[0], s1[0]); atomicAdd(&g_sq[0], s2[0]); }
}

// bn∘inorm∘lnorm collapses to v*scale_c + beta_c (lnorm global mean is 0).
__global__ void k_consts(const float* __restrict__ g, const float* __restrict__ lw,
                         const float* __restrict__ lb, int C, int n) {
    __shared__ float red[128];
    int c = threadIdx.x;
    float alpha = 0.f, v = 0.f, m = 0.f;
    if (c < C) {
        double md = g_sum[c] / (double)n;
        double vd = g_sq[c] / (double)n - md * md;
        if (vd < 0.0) vd = 0.0;
        m = (float)md; v = (float)vd;
        float r1 = rsqrtf(v + EPSC);
        float gv = g[c];
        float var1 = gv * gv * v * r1 * r1;       // var of BN output
        alpha = gv * r1 * rsqrtf(var1 + EPSC);    // inorm(bn(.)) slope
        red[c] = alpha * alpha * v;               // contribution to lnorm var
    } else {
        red[c] = 0.f;
    }
    __syncthreads();
    for (int o = 64; o; o >>= 1) {
        if (c < o) red[c] += red[c + o];
        __syncthreads();
    }
    float v2 = red[0] / (float)C;
    if (c < C) {
        float s = alpha * rsqrtf(v2 + EPSC) * lw[c];
        g_scale[c] = s;
        g_beta[c] = lb[c] - m * s;
    }
}

__global__ void k_final(const float* __restrict__ gy, float* __restrict__ out, int n) {
    int i = blockIdx.x * blockDim.x + threadIdx.x;
    if (i < n) out[i] = fmaf(gy[i], g_scale[0], g_beta[0]);
}

// ------------------------------ launch --------------------------------------
extern "C" void kernel_launch(void* const* d_in, const int* in_sizes, int n_in,
                              void* d_out, int out_size) {
    const float* x  = (const float*)d_in[0];
    const void*  ei = d_in[1];
    const float* W1 = (const float*)d_in[2];
    const float* g1 = (const float*)d_in[4];
    const float* lw1 = (const float*)d_in[6];
    const float* lb1 = (const float*)d_in[7];
    const float* W2 = (const float*)d_in[8];
    const float* g2 = (const float*)d_in[10];
    const float* lw2 = (const float*)d_in[12];
    const float* lb2 = (const float*)d_in[13];
    const float* W3 = (const float*)d_in[14];
    const float* g3 = (const float*)d_in[16];
    const float* lw3 = (const float*)d_in[18];
    const float* lb3 = (const float*)d_in[19];

    int n = in_sizes[0] / DIN;   // 100000
    int E = in_sizes[1] / 2;     // 400000
    int nb1024 = (n + 1023) / 1024;

    float* Hb; float* Ab; float* yb; float* gyb;
    cudaGetSymbolAddress((void**)&Hb,  g_H);
    cudaGetSymbolAddress((void**)&Ab,  g_A);
    cudaGetSymbolAddress((void**)&yb,  g_y);
    cudaGetSymbolAddress((void**)&gyb, g_gy);

    // ---- graph preprocessing ----
    k_zero_init<<<(n + 255) / 256, 256>>>(n);
    k_detect<<<16, 256>>>(ei);
    k_count<<<(E + 255) / 256, 256>>>(ei, E);
    k_dinv<<<(n + 255) / 256, 256>>>(n);
    k_scan_local<<<nb1024, 1024>>>(n, nb1024);
    k_scan_tops<<<1, 128>>>(nb1024);
    k_scan_final<<<(n + 255) / 256, 256>>>(n);
    k_fill<<<(E + 255) / 256, 256>>>(ei, E);

    // ---- layer 1: agg(x) @ W1 (stats fused), consts ----
    k_gather32<<<(n + 3) / 4, 128>>>(x, Ab, n);
    k_zero_stats<<<1, 128>>>();
    k_gemm<<<(n + BM - 1) / BM, 256>>>(Ab, W1, Hb, n, DIN);
    k_consts<<<1, 128>>>(g1, lw1, lb1, DHD, n);

    // ---- layer 2: agg(norm(h1)) @ W2 (norm fused into gather, stats fused) ----
    k_gather128n<<<(n + 3) / 4, 128>>>(Hb, Ab, n);
    k_zero_stats<<<1, 128>>>();
    k_gemm<<<(n + BM - 1) / BM, 256>>>(Ab, W2, Hb, n, DHD);
    k_consts<<<1, 128>>>(g2, lw2, lb2, DHD, n);

    // ---- layer 3: (norm(h2) @ W3) then scalar aggregation ----
    k_gemv<<<(n + 7) / 8, 256>>>(Hb, W3, yb, n);
    k_gather1<<<(n + 255) / 256, 256>>>(yb, gyb, n);
    k_zero_stats<<<1, 128>>>();
    k_stats1<<<256, 256>>>(gyb, n);
    k_consts<<<1, 128>>>(g3, lw3, lb3, 1, n);
    k_final<<<(n + 255) / 256, 256>>>(gyb, (float*)d_out, n);
}

// round 7
// speedup vs baseline: 1.6952x; 1.1961x over previous
#include <cuda_runtime.h>
#include <cuda_bf16.h>
#include <math.h>

#define NMAX 100000
#define EMAX 400000
#define DHD  128
#define DIN  32
#define GR   130   // K-major smem X-tile row stride (even: LDS.64-aligned; mod32=2: 2-way STS)
__device__ __constant__ float EPSC = 1e-5f;

// ------------- device scratch (no runtime allocation allowed) ---------------
__device__ float  g_H[(size_t)NMAX * DHD];     // layer-1 GEMM output
__device__ float  g_A[(size_t)NMAX * DHD];     // layer-2 GEMM output
__device__ float  g_dinv[NMAX];
__device__ int    g_cnt[NMAX];
__device__ int    g_fill[NMAX];
__device__ int    g_incl[NMAX];
__device__ int    g_rowptr[NMAX + 1];
__device__ int    g_col[EMAX];
__device__ float  g_val[EMAX];
__device__ float  g_y[NMAX];
__device__ float  g_gy[NMAX];
__device__ double g_sum[DHD];
__device__ double g_sq[DHD];
__device__ float  g_scale[DHD];
__device__ float  g_beta[DHD];
__device__ int    g_is32;
__device__ int    g_bsum[128];
__device__ int    g_tops[128];

// --------------------------- f32x2 helpers ----------------------------------
__device__ __forceinline__ void unpk2(unsigned long long v, float& lo, float& hi) {
    asm("mov.b64 {%0, %1}, %2;" : "=f"(lo), "=f"(hi) : "l"(v));
}
#define FMA2(c, a, b) asm("fma.rn.f32x2 %0, %1, %2, %0;" : "+l"(c) : "l"(a), "l"(b))

// --------------------------- small helpers ---------------------------------
__device__ __forceinline__ void load_edge(const void* ei, int E, int e, int& s, int& d) {
    if (g_is32) {
        const int* p = (const int*)ei;
        s = p[e]; d = p[E + e];
    } else {
        const long long* p = (const long long*)ei;
        s = (int)p[e]; d = (int)p[E + e];
    }
}

// ------------------------------- preprocessing ------------------------------
__global__ void k_zero_init(int n) {
    int i = blockIdx.x * blockDim.x + threadIdx.x;
    if (i < n) { g_cnt[i] = 0; g_fill[i] = 0; }
    if (i == 0) g_is32 = 0;
}

__global__ void k_detect(const void* ei) {
    int idx = blockIdx.x * blockDim.x + threadIdx.x;
    if (idx < 4096) {
        int w = ((const int*)ei)[2 * idx + 1];
        if (w != 0) g_is32 = 1;
    }
}

__global__ void k_count(const void* ei, int E) {
    int e = blockIdx.x * blockDim.x + threadIdx.x;
    if (e < E) {
        int s, d; load_edge(ei, E, e, s, d);
        atomicAdd(&g_cnt[d], 1);
    }
}

__global__ void k_dinv(int n) {
    int i = blockIdx.x * blockDim.x + threadIdx.x;
    if (i < n) g_dinv[i] = rsqrtf((float)(g_cnt[i] + 1));  // +1 self-loop
}

__global__ void k_scan_local(int n, int nblocks) {
    __shared__ int sh[1024];
    int t = threadIdx.x;
    int i = blockIdx.x * 1024 + t;
    int v = (i < n) ? g_cnt[i] : 0;
    sh[t] = v;
    __syncthreads();
    for (int off = 1; off < 1024; off <<= 1) {
        int add = (t >= off) ? sh[t - off] : 0;
        __syncthreads();
        sh[t] += add;
        __syncthreads();
    }
    if (i < n) g_incl[i] = sh[t];
    if (t == 1023) g_bsum[blockIdx.x] = sh[1023];
}

__global__ void k_scan_tops(int nblocks) {
    __shared__ int sh[128];
    int t = threadIdx.x;
    int orig = (t < nblocks) ? g_bsum[t] : 0;
    sh[t] = orig;
    __syncthreads();
    for (int off = 1; off < 128; off <<= 1) {
        int add = (t >= off) ? sh[t - off] : 0;
        __syncthreads();
        sh[t] += add;
        __syncthreads();
    }
    g_tops[t] = sh[t] - orig;
}

__global__ void k_scan_final(int n) {
    int i = blockIdx.x * blockDim.x + threadIdx.x;
    if (i < n) g_rowptr[i + 1] = g_incl[i] + g_tops[i >> 10];
    if (i == 0) g_rowptr[0] = 0;
}

__global__ void k_fill(const void* ei, int E) {
    int e = blockIdx.x * blockDim.x + threadIdx.x;
    if (e < E) {
        int s, d; load_edge(ei, E, e, s, d);
        int p = g_rowptr[d] + atomicAdd(&g_fill[d], 1);
        g_col[p] = s;
        g_val[p] = g_dinv[s] * g_dinv[d];
    }
}

// ==================== fused gather + GEMM (layer 1, K=32) ====================
// dyn smem: Xs[32][GR] floats, then Wd[32*128] float2 (duplicated interleaved)
__global__ void __launch_bounds__(256) k_gemm1f(const float* __restrict__ x,
                                                const float* __restrict__ W,
                                                float* __restrict__ Y, int n) {
    extern __shared__ float sm[];
    float (*Xs)[GR] = (float(*)[GR])sm;
    float2* Wd = (float2*)(sm + DIN * GR);
    int tid = threadIdx.x;
    int warp = tid >> 5, lane = tid & 31;
    int r0 = blockIdx.x * 128;

    // stage W as duplicated pairs, interleaved slot = (c&7)*16 + (c>>3)
#pragma unroll
    for (int l = 0; l < 4; l++) {
        int li = tid + l * 256;            // float4 index, 32*32 total
        int k = li >> 5;
        int c4 = (li & 31) * 4;
        float4 v = *(const float4*)(W + (size_t)k * DHD + c4);
        float vv[4] = {v.x, v.y, v.z, v.w};
#pragma unroll
        for (int m = 0; m < 4; m++) {
            int c = c4 + m;
            Wd[k * DHD + (c & 7) * 16 + (c >> 3)] = make_float2(vv[m], vv[m]);
        }
    }

    // gather phase: warp -> 16 nodes, lane = channel
    for (int i = 0; i < 16; i++) {
        int nl = warp * 16 + i;
        int node = r0 + nl;
        float acc = 0.f;
        if (node < n) {
            float di = g_dinv[node];
            acc = x[(size_t)node * DIN + lane] * di * di;
            int e0 = g_rowptr[node], e1 = g_rowptr[node + 1];
            int e = e0;
            for (; e + 1 < e1; e += 2) {
                int c0 = g_col[e], c1 = g_col[e + 1];
                float w0 = g_val[e], w1 = g_val[e + 1];
                acc += x[(size_t)c0 * DIN + lane] * w0 + x[(size_t)c1 * DIN + lane] * w1;
            }
            if (e < e1) acc += x[(size_t)g_col[e] * DIN + lane] * g_val[e];
        }
        Xs[lane][nl] = acc;
    }
    __syncthreads();

    int tx = tid & 15, ty = tid >> 4;
    const unsigned long long* Wq = (const unsigned long long*)Wd;
    unsigned long long acc[4][8];
#pragma unroll
    for (int i = 0; i < 4; i++)
#pragma unroll
        for (int j = 0; j < 8; j++) acc[i][j] = 0ULL;

#pragma unroll
    for (int k = 0; k < DIN; k++) {
        unsigned long long ap[4];
#pragma unroll
        for (int i = 0; i < 4; i++)
            ap[i] = *(const unsigned long long*)&Xs[k][ty * 8 + 2 * i];
#pragma unroll
        for (int j = 0; j < 8; j++) {
            unsigned long long bp = Wq[k * DHD + j * 16 + tx];
#pragma unroll
            for (int i = 0; i < 4; i++) FMA2(acc[i][j], ap[i], bp);
        }
    }

    // epilogue: write Y + per-channel stats
    float colsum[8], colsq[8];
#pragma unroll
    for (int j = 0; j < 8; j++) { colsum[j] = 0.f; colsq[j] = 0.f; }
#pragma unroll
    for (int i = 0; i < 4; i++) {
        float lo[8], hi[8];
#pragma unroll
        for (int j = 0; j < 8; j++) {
            unpk2(acc[i][j], lo[j], hi[j]);
            colsum[j] += lo[j] + hi[j];
            colsq[j] += lo[j] * lo[j] + hi[j] * hi[j];
        }
        int gr = r0 + ty * 8 + 2 * i;
        if (gr < n) {
            *(float4*)(Y + (size_t)gr * DHD + tx * 8) = make_float4(lo[0], lo[1], lo[2], lo[3]);
            *(float4*)(Y + (size_t)gr * DHD + tx * 8 + 4) = make_float4(lo[4], lo[5], lo[6], lo[7]);
        }
        if (gr + 1 < n) {
            *(float4*)(Y + (size_t)(gr + 1) * DHD + tx * 8) = make_float4(hi[0], hi[1], hi[2], hi[3]);
            *(float4*)(Y + (size_t)(gr + 1) * DHD + tx * 8 + 4) = make_float4(hi[4], hi[5], hi[6], hi[7]);
        }
    }
    __syncthreads();
    float* red = sm;                       // 16*128 floats
#pragma unroll
    for (int j = 0; j < 8; j++) red[ty * 128 + tx * 8 + j] = colsum[j];
    __syncthreads();
    if (tid < 128) {
        float s = 0.f;
#pragma unroll
        for (int t = 0; t < 16; t++) s += red[t * 128 + tid];
        atomicAdd(&g_sum[tid], (double)s);
    }
    __syncthreads();
#pragma unroll
    for (int j = 0; j < 8; j++) red[ty * 128 + tx * 8 + j] = colsq[j];
    __syncthreads();
    if (tid < 128) {
        float s = 0.f;
#pragma unroll
        for (int t = 0; t < 16; t++) s += red[t * 128 + tid];
        atomicAdd(&g_sq[tid], (double)s);
    }
}

// ============ fused norm-affine + relu + gather + GEMM (layer 2) ============
// dyn smem: Xs[128][GR] floats, then Wd[32*128] float2 (chunked over K)
__global__ void __launch_bounds__(256) k_gemm2f(const float* __restrict__ h,
                                                const float* __restrict__ W,
                                                float* __restrict__ Y, int n) {
    extern __shared__ float sm[];
    float (*Xs)[GR] = (float(*)[GR])sm;
    float2* Wd = (float2*)(sm + DHD * GR);
    int tid = threadIdx.x;
    int warp = tid >> 5, lane = tid & 31;
    int r0 = blockIdx.x * 128;

    // per-lane norm constants for channels lane+32j
    float sc0 = g_scale[lane], sc1 = g_scale[lane + 32],
          sc2 = g_scale[lane + 64], sc3 = g_scale[lane + 96];
    float bt0 = g_beta[lane], bt1 = g_beta[lane + 32],
          bt2 = g_beta[lane + 64], bt3 = g_beta[lane + 96];

    // gather phase: warp -> 16 nodes; lane covers channels lane+32j
    for (int i = 0; i < 16; i++) {
        int nl = warp * 16 + i;
        int node = r0 + nl;
        float a0 = 0.f, a1 = 0.f, a2 = 0.f, a3 = 0.f;
        if (node < n) {
            float di = g_dinv[node];
            float ws = di * di;
            const float* hr = h + (size_t)node * DHD;
            a0 = fmaxf(fmaf(hr[lane],      sc0, bt0), 0.f) * ws;
            a1 = fmaxf(fmaf(hr[lane + 32], sc1, bt1), 0.f) * ws;
            a2 = fmaxf(fmaf(hr[lane + 64], sc2, bt2), 0.f) * ws;
            a3 = fmaxf(fmaf(hr[lane + 96], sc3, bt3), 0.f) * ws;
            int e0 = g_rowptr[node], e1 = g_rowptr[node + 1];
            int e = e0;
            for (; e + 1 < e1; e += 2) {
                int c0 = g_col[e], c1 = g_col[e + 1];
                float w0 = g_val[e], w1 = g_val[e + 1];
                const float* h0 = h + (size_t)c0 * DHD;
                const float* h1 = h + (size_t)c1 * DHD;
                a0 += fmaxf(fmaf(h0[lane],      sc0, bt0), 0.f) * w0
                    + fmaxf(fmaf(h1[lane],      sc0, bt0), 0.f) * w1;
                a1 += fmaxf(fmaf(h0[lane + 32], sc1, bt1), 0.f) * w0
                    + fmaxf(fmaf(h1[lane + 32], sc1, bt1), 0.f) * w1;
                a2 += fmaxf(fmaf(h0[lane + 64], sc2, bt2), 0.f) * w0
                    + fmaxf(fmaf(h1[lane + 64], sc2, bt2), 0.f) * w1;
                a3 += fmaxf(fmaf(h0[lane + 96], sc3, bt3), 0.f) * w0
                    + fmaxf(fmaf(h1[lane + 96], sc3, bt3), 0.f) * w1;
            }
            if (e < e1) {
                int c0 = g_col[e]; float w0 = g_val[e];
                const float* h0 = h + (size_t)c0 * DHD;
                a0 += fmaxf(fmaf(h0[lane],      sc0, bt0), 0.f) * w0;
                a1 += fmaxf(fmaf(h0[lane + 32], sc1, bt1), 0.f) * w0;
                a2 += fmaxf(fmaf(h0[lane + 64], sc2, bt2), 0.f) * w0;
                a3 += fmaxf(fmaf(h0[lane + 96], sc3, bt3), 0.f) * w0;
            }
        }
        Xs[lane][nl] = a0;
        Xs[lane + 32][nl] = a1;
        Xs[lane + 64][nl] = a2;
        Xs[lane + 96][nl] = a3;
    }

    int tx = tid & 15, ty = tid >> 4;
    const unsigned long long* Wq = (const unsigned long long*)Wd;
    unsigned long long acc[4][8];
#pragma unroll
    for (int i = 0; i < 4; i++)
#pragma unroll
        for (int j = 0; j < 8; j++) acc[i][j] = 0ULL;

    for (int kc = 0; kc < DHD; kc += 32) {
        __syncthreads();   // gather done (first iter) / previous chunk consumed
#pragma unroll
        for (int l = 0; l < 4; l++) {
            int li = tid + l * 256;
            int k = li >> 5;
            int c4 = (li & 31) * 4;
            float4 v = *(const float4*)(W + (size_t)(kc + k) * DHD + c4);
            float vv[4] = {v.x, v.y, v.z, v.w};
#pragma unroll
            for (int m = 0; m < 4; m++) {
                int c = c4 + m;
                Wd[k * DHD + (c & 7) * 16 + (c >> 3)] = make_float2(vv[m], vv[m]);
            }
        }
        __syncthreads();
#pragma unroll
        for (int k = 0; k < 32; k++) {
            unsigned long long ap[4];
#pragma unroll
            for (int i = 0; i < 4; i++)
                ap[i] = *(const unsigned long long*)&Xs[kc + k][ty * 8 + 2 * i];
#pragma unroll
            for (int j = 0; j < 8; j++) {
                unsigned long long bp = Wq[k * DHD + j * 16 + tx];
#pragma unroll
                for (int i = 0; i < 4; i++) FMA2(acc[i][j], ap[i], bp);
            }
        }
    }

    // epilogue: write Y + per-channel stats
    float colsum[8], colsq[8];
#pragma unroll
    for (int j = 0; j < 8; j++) { colsum[j] = 0.f; colsq[j] = 0.f; }
#pragma unroll
    for (int i = 0; i < 4; i++) {
        float lo[8], hi[8];
#pragma unroll
        for (int j = 0; j < 8; j++) {
            unpk2(acc[i][j], lo[j], hi[j]);
            colsum[j] += lo[j] + hi[j];
            colsq[j] += lo[j] * lo[j] + hi[j] * hi[j];
        }
        int gr = r0 + ty * 8 + 2 * i;
        if (gr < n) {
            *(float4*)(Y + (size_t)gr * DHD + tx * 8) = make_float4(lo[0], lo[1], lo[2], lo[3]);
            *(float4*)(Y + (size_t)gr * DHD + tx * 8 + 4) = make_float4(lo[4], lo[5], lo[6], lo[7]);
        }
        if (gr + 1 < n) {
            *(float4*)(Y + (size_t)(gr + 1) * DHD + tx * 8) = make_float4(hi[0], hi[1], hi[2], hi[3]);
            *(float4*)(Y + (size_t)(gr + 1) * DHD + tx * 8 + 4) = make_float4(hi[4], hi[5], hi[6], hi[7]);
        }
    }
    __syncthreads();
    float* red = sm;
#pragma unroll
    for (int j = 0; j < 8; j++) red[ty * 128 + tx * 8 + j] = colsum[j];
    __syncthreads();
    if (tid < 128) {
        float s = 0.f;
#pragma unroll
        for (int t = 0; t < 16; t++) s += red[t * 128 + tid];
        atomicAdd(&g_sum[tid], (double)s);
    }
    __syncthreads();
#pragma unroll
    for (int j = 0; j < 8; j++) red[ty * 128 + tx * 8 + j] = colsq[j];
    __syncthreads();
    if (tid < 128) {
        float s = 0.f;
#pragma unroll
        for (int t = 0; t < 16; t++) s += red[t * 128 + tid];
        atomicAdd(&g_sq[tid], (double)s);
    }
}

// ---- GEMV with fused affine+relu on input: y = relu(H*s+b) @ w3 -----------
__global__ void __launch_bounds__(256) k_gemv(const float* __restrict__ H,
                                              const float* __restrict__ W3,
                                              float* __restrict__ y, int n) {
    __shared__ float w[DHD], sc[DHD], bt[DHD];
    if (threadIdx.x < DHD) {
        w[threadIdx.x] = W3[threadIdx.x];
        sc[threadIdx.x] = g_scale[threadIdx.x];
        bt[threadIdx.x] = g_beta[threadIdx.x];
    }
    __syncthreads();
    int warp = threadIdx.x >> 5, lane = threadIdx.x & 31;
    int row = blockIdx.x * 8 + warp;
    if (row >= n) return;
    const float* h = H + (size_t)row * DHD;
    float s = 0.f;
#pragma unroll
    for (int k = 0; k < 4; k++) {
        int c = lane + 32 * k;
        float v = fmaxf(fmaf(h[c], sc[c], bt[c]), 0.f);
        s = fmaf(v, w[c], s);
    }
#pragma unroll
    for (int o = 16; o; o >>= 1) s += __shfl_xor_sync(0xFFFFFFFFu, s, o);
    if (lane == 0) y[row] = s;
}

__global__ void k_gather1(const float* __restrict__ y, float* __restrict__ out, int n) {
    int i = blockIdx.x * blockDim.x + threadIdx.x;
    if (i >= n) return;
    float di = g_dinv[i];
    float acc = y[i] * di * di;
    int e0 = g_rowptr[i], e1 = g_rowptr[i + 1];
    int e = e0;
    for (; e + 3 < e1; e += 4) {
        int c0 = g_col[e], c1 = g_col[e + 1], c2 = g_col[e + 2], c3 = g_col[e + 3];
        float y0 = y[c0], y1 = y[c1], y2 = y[c2], y3 = y[c3];
        acc += y0 * g_val[e] + y1 * g_val[e + 1] + y2 * g_val[e + 2] + y3 * g_val[e + 3];
    }
    for (; e < e1; e++) acc += y[g_col[e]] * g_val[e];
    out[i] = acc;
}

// ---- stats ----
__global__ void k_zero_stats() {
    int c = threadIdx.x;
    g_sum[c] = 0.0; g_sq[c] = 0.0;
}

__global__ void k_stats1(const float* __restrict__ v, int n) {
    __shared__ double s1[256], s2[256];
    int t = threadIdx.x;
    double s = 0.0, ss = 0.0;
    for (int i = blockIdx.x * 256 + t; i < n; i += gridDim.x * 256) {
        float x = v[i];
        s += x; ss += (double)x * (double)x;
    }
    s1[t] = s; s2[t] = ss;
    __syncthreads();
    for (int o = 128; o; o >>= 1) {
        if (t < o) { s1[t] += s1[t + o]; s2[t] += s2[t + o]; }
        __syncthreads();
    }
    if (t == 0) { atomicAdd(&g_sum[0], s1[0]); atomicAdd(&g_sq[0], s2[0]); }
}

// bn∘inorm∘lnorm collapses to v*scale_c + beta_c (lnorm global mean is 0).
__global__ void k_consts(const float* __restrict__ g, const float* __restrict__ lw,
                         const float* __restrict__ lb, int C, int n) {
    __shared__ float red[128];
    int c = threadIdx.x;
    float alpha = 0.f, v = 0.f, m = 0.f;
    if (c < C) {
        double md = g_sum[c] / (double)n;
        double vd = g_sq[c] / (double)n - md * md;
        if (vd < 0.0) vd = 0.0;
        m = (float)md; v = (float)vd;
        float r1 = rsqrtf(v + EPSC);
        float gv = g[c];
        float var1 = gv * gv * v * r1 * r1;       // var of BN output
        alpha = gv * r1 * rsqrtf(var1 + EPSC);    // inorm(bn(.)) slope
        red[c] = alpha * alpha * v;               // contribution to lnorm var
    } else {
        red[c] = 0.f;
    }
    __syncthreads();
    for (int o = 64; o; o >>= 1) {
        if (c < o) red[c] += red[c + o];
        __syncthreads();
    }
    float v2 = red[0] / (float)C;
    if (c < C) {
        float s = alpha * rsqrtf(v2 + EPSC) * lw[c];
        g_scale[c] = s;
        g_beta[c] = lb[c] - m * s;
    }
}

__global__ void k_final(const float* __restrict__ gy, float* __restrict__ out, int n) {
    int i = blockIdx.x * blockDim.x + threadIdx.x;
    if (i < n) out[i] = fmaf(gy[i], g_scale[0], g_beta[0]);
}

// ------------------------------ launch --------------------------------------
extern "C" void kernel_launch(void* const* d_in, const int* in_sizes, int n_in,
                              void* d_out, int out_size) {
    const float* x  = (const float*)d_in[0];
    const void*  ei = d_in[1];
    const float* W1 = (const float*)d_in[2];
    const float* g1 = (const float*)d_in[4];
    const float* lw1 = (const float*)d_in[6];
    const float* lb1 = (const float*)d_in[7];
    const float* W2 = (const float*)d_in[8];
    const float* g2 = (const float*)d_in[10];
    const float* lw2 = (const float*)d_in[12];
    const float* lb2 = (const float*)d_in[13];
    const float* W3 = (const float*)d_in[14];
    const float* g3 = (const float*)d_in[16];
    const float* lw3 = (const float*)d_in[18];
    const float* lb3 = (const float*)d_in[19];

    int n = in_sizes[0] / DIN;   // 100000
    int E = in_sizes[1] / 2;     // 400000
    int nb1024 = (n + 1023) / 1024;

    const int SM1 = DIN * GR * 4 + DIN * DHD * 8;   // 16640 + 32768 = 49408
    const int SM2 = DHD * GR * 4 + 32 * DHD * 8;    // 66560 + 32768 = 99328
    cudaFuncSetAttribute(k_gemm1f, cudaFuncAttributeMaxDynamicSharedMemorySize, SM1);
    cudaFuncSetAttribute(k_gemm2f, cudaFuncAttributeMaxDynamicSharedMemorySize, SM2);

    float* Hb; float* Ab; float* yb; float* gyb;
    cudaGetSymbolAddress((void**)&Hb,  g_H);
    cudaGetSymbolAddress((void**)&Ab,  g_A);
    cudaGetSymbolAddress((void**)&yb,  g_y);
    cudaGetSymbolAddress((void**)&gyb, g_gy);

    int nblk = (n + 127) / 128;

    // ---- graph preprocessing ----
    k_zero_init<<<(n + 255) / 256, 256>>>(n);
    k_detect<<<16, 256>>>(ei);
    k_count<<<(E + 255) / 256, 256>>>(ei, E);
    k_dinv<<<(n + 255) / 256, 256>>>(n);
    k_scan_local<<<nb1024, 1024>>>(n, nb1024);
    k_scan_tops<<<1, 128>>>(nb1024);
    k_scan_final<<<(n + 255) / 256, 256>>>(n);
    k_fill<<<(E + 255) / 256, 256>>>(ei, E);

    // ---- layer 1: fused gather(x) + GEMM1 (+stats), consts ----
    k_zero_stats<<<1, 128>>>();
    k_gemm1f<<<nblk, 256, SM1>>>(x, W1, Hb, n);
    k_consts<<<1, 128>>>(g1, lw1, lb1, DHD, n);

    // ---- layer 2: fused norm+relu+gather(h1) + GEMM2 (+stats), consts ----
    k_zero_stats<<<1, 128>>>();
    k_gemm2f<<<nblk, 256, SM2>>>(Hb, W2, Ab, n);
    k_consts<<<1, 128>>>(g2, lw2, lb2, DHD, n);

    // ---- layer 3: (norm(h2) @ W3) then scalar aggregation ----
    k_gemv<<<(n + 7) / 8, 256>>>(Ab, W3, yb, n);
    k_gather1<<<(n + 255) / 256, 256>>>(yb, gyb, n);
    k_zero_stats<<<1, 128>>>();
    k_stats1<<<256, 256>>>(gyb, n);
    k_consts<<<1, 128>>>(g3, lw3, lb3, 1, n);
    k_final<<<(n + 255) / 256, 256>>>(gyb, (float*)d_out, n);
}

// round 12
// speedup vs baseline: 1.8403x; 1.0856x over previous
#include <cuda_runtime.h>
#include <cuda_bf16.h>
#include <math.h>

#define NMAX 100000
#define EMAX 400000
#define DHD  128
#define DIN  32
#define GR   130   // K-major smem X-tile row stride (even: LDS.64-aligned; mod32=2: 2-way STS)
__device__ __constant__ float EPSC = 1e-5f;

// ------------- device scratch (no runtime allocation allowed) ---------------
__device__ float  g_H[(size_t)NMAX * DHD];     // layer-1 GEMM output
__device__ float  g_A[(size_t)NMAX * DHD];     // layer-2 GEMM output
__device__ float  g_dinv[NMAX];
__device__ int    g_cnt[NMAX];
__device__ int    g_fill[NMAX];
__device__ int    g_incl[NMAX];
__device__ int    g_rowptr[NMAX + 1];
__device__ int    g_col[EMAX];
__device__ float  g_val[EMAX];
__device__ float  g_y[NMAX];
__device__ float  g_gy[NMAX];
__device__ double g_sum[DHD];
__device__ double g_sq[DHD];
__device__ float  g_scale[DHD];
__device__ float  g_beta[DHD];
__device__ int    g_is32 = 0;   // only ever set to 1 (idempotent across graph replays)
__device__ int    g_bsum[128];
__device__ int    g_tops[128];

// --------------------------- f32x2 helpers ----------------------------------
__device__ __forceinline__ void unpk2(unsigned long long v, float& lo, float& hi) {
    asm("mov.b64 {%0, %1}, %2;" : "=f"(lo), "=f"(hi) : "l"(v));
}
#define FMA2(c, a, b) asm("fma.rn.f32x2 %0, %1, %2, %0;" : "+l"(c) : "l"(a), "l"(b))

// --------------------------- small helpers ---------------------------------
__device__ __forceinline__ void load_edge(const void* ei, int E, int e, int& s, int& d) {
    if (g_is32) {
        const int* p = (const int*)ei;
        s = p[e]; d = p[E + e];
    } else {
        const long long* p = (const long long*)ei;
        s = (int)p[e]; d = (int)p[E + e];
    }
}

// ---------------- preprocessing (merged: zero + detect + stats-zero) --------
__global__ void k_zero_init(const void* ei, int n) {
    int i = blockIdx.x * blockDim.x + threadIdx.x;
    if (i < n) { g_cnt[i] = 0; g_fill[i] = 0; }
    if (i < DHD) { g_sum[i] = 0.0; g_sq[i] = 0.0; }
    if (i < 4096) {                     // int32 vs int64 detect (set-only)
        int w = ((const int*)ei)[2 * i + 1];
        if (w != 0) g_is32 = 1;
    }
}

__global__ void k_count(const void* ei, int E) {
    int e = blockIdx.x * blockDim.x + threadIdx.x;
    if (e < E) {
        int s, d; load_edge(ei, E, e, s, d);
        atomicAdd(&g_cnt[d], 1);
    }
}

// scan of g_cnt (local phase) + dinv computation folded in
__global__ void k_scan_local(int n, int nblocks) {
    __shared__ int sh[1024];
    int t = threadIdx.x;
    int i = blockIdx.x * 1024 + t;
    int v = (i < n) ? g_cnt[i] : 0;
    if (i < n) g_dinv[i] = rsqrtf((float)(v + 1));   // +1 self-loop
    sh[t] = v;
    __syncthreads();
    for (int off = 1; off < 1024; off <<= 1) {
        int add = (t >= off) ? sh[t - off] : 0;
        __syncthreads();
        sh[t] += add;
        __syncthreads();
    }
    if (i < n) g_incl[i] = sh[t];
    if (t == 1023) g_bsum[blockIdx.x] = sh[1023];
}

__global__ void k_scan_tops(int nblocks) {
    __shared__ int sh[128];
    int t = threadIdx.x;
    int orig = (t < nblocks) ? g_bsum[t] : 0;
    sh[t] = orig;
    __syncthreads();
    for (int off = 1; off < 128; off <<= 1) {
        int add = (t >= off) ? sh[t - off] : 0;
        __syncthreads();
        sh[t] += add;
        __syncthreads();
    }
    g_tops[t] = sh[t] - orig;
}

__global__ void k_scan_final(int n) {
    int i = blockIdx.x * blockDim.x + threadIdx.x;
    if (i < n) g_rowptr[i + 1] = g_incl[i] + g_tops[i >> 10];
    if (i == 0) g_rowptr[0] = 0;
}

__global__ void k_fill(const void* ei, int E) {
    int e = blockIdx.x * blockDim.x + threadIdx.x;
    if (e < E) {
        int s, d; load_edge(ei, E, e, s, d);
        int p = g_rowptr[d] + atomicAdd(&g_fill[d], 1);
        g_col[p] = s;
        g_val[p] = g_dinv[s] * g_dinv[d];
    }
}

// ==================== fused gather + GEMM (layer 1, K=32) ====================
// dyn smem: Xs[32][GR] floats, then Wd[32*128] float2 (duplicated interleaved)
__global__ void __launch_bounds__(256) k_gemm1f(const float* __restrict__ x,
                                                const float* __restrict__ W,
                                                float* __restrict__ Y, int n) {
    extern __shared__ float sm[];
    float (*Xs)[GR] = (float(*)[GR])sm;
    float2* Wd = (float2*)(sm + DIN * GR);
    int tid = threadIdx.x;
    int warp = tid >> 5, lane = tid & 31;
    int r0 = blockIdx.x * 128;

    // stage W as duplicated pairs, interleaved slot = (c&7)*16 + (c>>3)
#pragma unroll
    for (int l = 0; l < 4; l++) {
        int li = tid + l * 256;            // float4 index, 32*32 total
        int k = li >> 5;
        int c4 = (li & 31) * 4;
        float4 v = *(const float4*)(W + (size_t)k * DHD + c4);
        float vv[4] = {v.x, v.y, v.z, v.w};
#pragma unroll
        for (int m = 0; m < 4; m++) {
            int c = c4 + m;
            Wd[k * DHD + (c & 7) * 16 + (c >> 3)] = make_float2(vv[m], vv[m]);
        }
    }

    // gather phase: warp -> 16 nodes, lane = channel, 4-edge unroll for MLP
    for (int i = 0; i < 16; i++) {
        int nl = warp * 16 + i;
        int node = r0 + nl;
        float acc = 0.f;
        if (node < n) {
            float di = g_dinv[node];
            acc = x[(size_t)node * DIN + lane] * di * di;
            int e0 = g_rowptr[node], e1 = g_rowptr[node + 1];
            int e = e0;
            for (; e + 3 < e1; e += 4) {
                int c0 = g_col[e], c1 = g_col[e + 1], c2 = g_col[e + 2], c3 = g_col[e + 3];
                float w0 = g_val[e], w1 = g_val[e + 1], w2 = g_val[e + 2], w3 = g_val[e + 3];
                float v0 = x[(size_t)c0 * DIN + lane];
                float v1 = x[(size_t)c1 * DIN + lane];
                float v2 = x[(size_t)c2 * DIN + lane];
                float v3 = x[(size_t)c3 * DIN + lane];
                acc += v0 * w0 + v1 * w1 + v2 * w2 + v3 * w3;
            }
            for (; e < e1; e++) acc += x[(size_t)g_col[e] * DIN + lane] * g_val[e];
        }
        Xs[lane][nl] = acc;
    }
    __syncthreads();

    int tx = tid & 15, ty = tid >> 4;
    const unsigned long long* Wq = (const unsigned long long*)Wd;
    unsigned long long acc[4][8];
#pragma unroll
    for (int i = 0; i < 4; i++)
#pragma unroll
        for (int j = 0; j < 8; j++) acc[i][j] = 0ULL;

#pragma unroll
    for (int k = 0; k < DIN; k++) {
        unsigned long long ap[4];
#pragma unroll
        for (int i = 0; i < 4; i++)
            ap[i] = *(const unsigned long long*)&Xs[k][ty * 8 + 2 * i];
#pragma unroll
        for (int j = 0; j < 8; j++) {
            unsigned long long bp = Wq[k * DHD + j * 16 + tx];
#pragma unroll
            for (int i = 0; i < 4; i++) FMA2(acc[i][j], ap[i], bp);
        }
    }

    // epilogue: write Y + per-channel stats
    float colsum[8], colsq[8];
#pragma unroll
    for (int j = 0; j < 8; j++) { colsum[j] = 0.f; colsq[j] = 0.f; }
#pragma unroll
    for (int i = 0; i < 4; i++) {
        float lo[8], hi[8];
#pragma unroll
        for (int j = 0; j < 8; j++) {
            unpk2(acc[i][j], lo[j], hi[j]);
            colsum[j] += lo[j] + hi[j];
            colsq[j] += lo[j] * lo[j] + hi[j] * hi[j];
        }
        int gr = r0 + ty * 8 + 2 * i;
        if (gr < n) {
            *(float4*)(Y + (size_t)gr * DHD + tx * 8) = make_float4(lo[0], lo[1], lo[2], lo[3]);
            *(float4*)(Y + (size_t)gr * DHD + tx * 8 + 4) = make_float4(lo[4], lo[5], lo[6], lo[7]);
        }
        if (gr + 1 < n) {
            *(float4*)(Y + (size_t)(gr + 1) * DHD + tx * 8) = make_float4(hi[0], hi[1], hi[2], hi[3]);
            *(float4*)(Y + (size_t)(gr + 1) * DHD + tx * 8 + 4) = make_float4(hi[4], hi[5], hi[6], hi[7]);
        }
    }
    __syncthreads();
    float* red = sm;                       // 16*128 floats
#pragma unroll
    for (int j = 0; j < 8; j++) red[ty * 128 + tx * 8 + j] = colsum[j];
    __syncthreads();
    if (tid < 128) {
        float s = 0.f;
#pragma unroll
        for (int t = 0; t < 16; t++) s += red[t * 128 + tid];
        atomicAdd(&g_sum[tid], (double)s);
    }
    __syncthreads();
#pragma unroll
    for (int j = 0; j < 8; j++) red[ty * 128 + tx * 8 + j] = colsq[j];
    __syncthreads();
    if (tid < 128) {
        float s = 0.f;
#pragma unroll
        for (int t = 0; t < 16; t++) s += red[t * 128 + tid];
        atomicAdd(&g_sq[tid], (double)s);
    }
}

// ============ fused norm-affine + relu + gather + GEMM (layer 2) ============
// dyn smem: Xs[128][GR] floats, then Wd[32*128] float2 (chunked over K)
__global__ void __launch_bounds__(256) k_gemm2f(const float* __restrict__ h,
                                                const float* __restrict__ W,
                                                float* __restrict__ Y, int n) {
    extern __shared__ float sm[];
    float (*Xs)[GR] = (float(*)[GR])sm;
    float2* Wd = (float2*)(sm + DHD * GR);
    int tid = threadIdx.x;
    int warp = tid >> 5, lane = tid & 31;
    int r0 = blockIdx.x * 128;

    // per-lane norm constants for channels lane+32j
    float sc0 = g_scale[lane], sc1 = g_scale[lane + 32],
          sc2 = g_scale[lane + 64], sc3 = g_scale[lane + 96];
    float bt0 = g_beta[lane], bt1 = g_beta[lane + 32],
          bt2 = g_beta[lane + 64], bt3 = g_beta[lane + 96];

    // gather phase: warp -> 16 nodes; lane covers channels lane+32j; 4-edge unroll
    for (int i = 0; i < 16; i++) {
        int nl = warp * 16 + i;
        int node = r0 + nl;
        float a0 = 0.f, a1 = 0.f, a2 = 0.f, a3 = 0.f;
        if (node < n) {
            float di = g_dinv[node];
            float ws = di * di;
            const float* hr = h + (size_t)node * DHD;
            a0 = fmaxf(fmaf(hr[lane],      sc0, bt0), 0.f) * ws;
            a1 = fmaxf(fmaf(hr[lane + 32], sc1, bt1), 0.f) * ws;
            a2 = fmaxf(fmaf(hr[lane + 64], sc2, bt2), 0.f) * ws;
            a3 = fmaxf(fmaf(hr[lane + 96], sc3, bt3), 0.f) * ws;
            int e0 = g_rowptr[node], e1 = g_rowptr[node + 1];
            int e = e0;
            for (; e + 3 < e1; e += 4) {
                int c0 = g_col[e], c1 = g_col[e + 1], c2 = g_col[e + 2], c3 = g_col[e + 3];
                float w0 = g_val[e], w1 = g_val[e + 1], w2 = g_val[e + 2], w3 = g_val[e + 3];
                const float* h0 = h + (size_t)c0 * DHD;
                const float* h1 = h + (size_t)c1 * DHD;
                const float* h2 = h + (size_t)c2 * DHD;
                const float* h3 = h + (size_t)c3 * DHD;
                float v00 = h0[lane],      v10 = h1[lane],      v20 = h2[lane],      v30 = h3[lane];
                float v01 = h0[lane + 32], v11 = h1[lane + 32], v21 = h2[lane + 32], v31 = h3[lane + 32];
                float v02 = h0[lane + 64], v12 = h1[lane + 64], v22 = h2[lane + 64], v32 = h3[lane + 64];
                float v03 = h0[lane + 96], v13 = h1[lane + 96], v23 = h2[lane + 96], v33 = h3[lane + 96];
                a0 += fmaxf(fmaf(v00, sc0, bt0), 0.f) * w0 + fmaxf(fmaf(v10, sc0, bt0), 0.f) * w1
                    + fmaxf(fmaf(v20, sc0, bt0), 0.f) * w2 + fmaxf(fmaf(v30, sc0, bt0), 0.f) * w3;
                a1 += fmaxf(fmaf(v01, sc1, bt1), 0.f) * w0 + fmaxf(fmaf(v11, sc1, bt1), 0.f) * w1
                    + fmaxf(fmaf(v21, sc1, bt1), 0.f) * w2 + fmaxf(fmaf(v31, sc1, bt1), 0.f) * w3;
                a2 += fmaxf(fmaf(v02, sc2, bt2), 0.f) * w0 + fmaxf(fmaf(v12, sc2, bt2), 0.f) * w1
                    + fmaxf(fmaf(v22, sc2, bt2), 0.f) * w2 + fmaxf(fmaf(v32, sc2, bt2), 0.f) * w3;
                a3 += fmaxf(fmaf(v03, sc3, bt3), 0.f) * w0 + fmaxf(fmaf(v13, sc3, bt3), 0.f) * w1
                    + fmaxf(fmaf(v23, sc3, bt3), 0.f) * w2 + fmaxf(fmaf(v33, sc3, bt3), 0.f) * w3;
            }
            for (; e < e1; e++) {
                int c0 = g_col[e]; float w0 = g_val[e];
                const float* h0 = h + (size_t)c0 * DHD;
                a0 += fmaxf(fmaf(h0[lane],      sc0, bt0), 0.f) * w0;
                a1 += fmaxf(fmaf(h0[lane + 32], sc1, bt1), 0.f) * w0;
                a2 += fmaxf(fmaf(h0[lane + 64], sc2, bt2), 0.f) * w0;
                a3 += fmaxf(fmaf(h0[lane + 96], sc3, bt3), 0.f) * w0;
            }
        }
        Xs[lane][nl] = a0;
        Xs[lane + 32][nl] = a1;
        Xs[lane + 64][nl] = a2;
        Xs[lane + 96][nl] = a3;
    }

    int tx = tid & 15, ty = tid >> 4;
    const unsigned long long* Wq = (const unsigned long long*)Wd;
    unsigned long long acc[4][8];
#pragma unroll
    for (int i = 0; i < 4; i++)
#pragma unroll
        for (int j = 0; j < 8; j++) acc[i][j] = 0ULL;

    for (int kc = 0; kc < DHD; kc += 32) {
        __syncthreads();   // gather done (first iter) / previous chunk consumed
#pragma unroll
        for (int l = 0; l < 4; l++) {
            int li = tid + l * 256;
            int k = li >> 5;
            int c4 = (li & 31) * 4;
            float4 v = *(const float4*)(W + (size_t)(kc + k) * DHD + c4);
            float vv[4] = {v.x, v.y, v.z, v.w};
#pragma unroll
            for (int m = 0; m < 4; m++) {
                int c = c4 + m;
                Wd[k * DHD + (c & 7) * 16 + (c >> 3)] = make_float2(vv[m], vv[m]);
            }
        }
        __syncthreads();
#pragma unroll
        for (int k = 0; k < 32; k++) {
            unsigned long long ap[4];
#pragma unroll
            for (int i = 0; i < 4; i++)
                ap[i] = *(const unsigned long long*)&Xs[kc + k][ty * 8 + 2 * i];
#pragma unroll
            for (int j = 0; j < 8; j++) {
                unsigned long long bp = Wq[k * DHD + j * 16 + tx];
#pragma unroll
                for (int i = 0; i < 4; i++) FMA2(acc[i][j], ap[i], bp);
            }
        }
    }

    // epilogue: write Y + per-channel stats
    float colsum[8], colsq[8];
#pragma unroll
    for (int j = 0; j < 8; j++) { colsum[j] = 0.f; colsq[j] = 0.f; }
#pragma unroll
    for (int i = 0; i < 4; i++) {
        float lo[8], hi[8];
#pragma unroll
        for (int j = 0; j < 8; j++) {
            unpk2(acc[i][j], lo[j], hi[j]);
            colsum[j] += lo[j] + hi[j];
            colsq[j] += lo[j] * lo[j] + hi[j] * hi[j];
        }
        int gr = r0 + ty * 8 + 2 * i;
        if (gr < n) {
            *(float4*)(Y + (size_t)gr * DHD + tx * 8) = make_float4(lo[0], lo[1], lo[2], lo[3]);
            *(float4*)(Y + (size_t)gr * DHD + tx * 8 + 4) = make_float4(lo[4], lo[5], lo[6], lo[7]);
        }
        if (gr + 1 < n) {
            *(float4*)(Y + (size_t)(gr + 1) * DHD + tx * 8) = make_float4(hi[0], hi[1], hi[2], hi[3]);
            *(float4*)(Y + (size_t)(gr + 1) * DHD + tx * 8 + 4) = make_float4(hi[4], hi[5], hi[6], hi[7]);
        }
    }
    __syncthreads();
    float* red = sm;
#pragma unroll
    for (int j = 0; j < 8; j++) red[ty * 128 + tx * 8 + j] = colsum[j];
    __syncthreads();
    if (tid < 128) {
        float s = 0.f;
#pragma unroll
        for (int t = 0; t < 16; t++) s += red[t * 128 + tid];
        atomicAdd(&g_sum[tid], (double)s);
    }
    __syncthreads();
#pragma unroll
    for (int j = 0; j < 8; j++) red[ty * 128 + tx * 8 + j] = colsq[j];
    __syncthreads();
    if (tid < 128) {
        float s = 0.f;
#pragma unroll
        for (int t = 0; t < 16; t++) s += red[t * 128 + tid];
        atomicAdd(&g_sq[tid], (double)s);
    }
}

// ---- GEMV with fused affine+relu on input: y = relu(H*s+b) @ w3 -----------
__global__ void __launch_bounds__(256) k_gemv(const float* __restrict__ H,
                                              const float* __restrict__ W3,
                                              float* __restrict__ y, int n) {
    __shared__ float w[DHD], sc[DHD], bt[DHD];
    if (threadIdx.x < DHD) {
        w[threadIdx.x] = W3[threadIdx.x];
        sc[threadIdx.x] = g_scale[threadIdx.x];
        bt[threadIdx.x] = g_beta[threadIdx.x];
    }
    __syncthreads();
    int warp = threadIdx.x >> 5, lane = threadIdx.x & 31;
    int row = blockIdx.x * 8 + warp;
    if (row >= n) return;
    const float* h = H + (size_t)row * DHD;
    float s = 0.f;
#pragma unroll
    for (int k = 0; k < 4; k++) {
        int c = lane + 32 * k;
        float v = fmaxf(fmaf(h[c], sc[c], bt[c]), 0.f);
        s = fmaf(v, w[c], s);
    }
#pragma unroll
    for (int o = 16; o; o >>= 1) s += __shfl_xor_sync(0xFFFFFFFFu, s, o);
    if (lane == 0) y[row] = s;
}

// ---- layer-3 scalar gather with fused stats (block-reduce + atomic) --------
__global__ void k_gather1s(const float* __restrict__ y, float* __restrict__ out, int n) {
    __shared__ float s1[256], s2[256];
    int t = threadIdx.x;
    int i = blockIdx.x * blockDim.x + t;
    float acc = 0.f;
    if (i < n) {
        float di = g_dinv[i];
        acc = y[i] * di * di;
        int e0 = g_rowptr[i], e1 = g_rowptr[i + 1];
        int e = e0;
        for (; e + 3 < e1; e += 4) {
            int c0 = g_col[e], c1 = g_col[e + 1], c2 = g_col[e + 2], c3 = g_col[e + 3];
            float y0 = y[c0], y1 = y[c1], y2 = y[c2], y3 = y[c3];
            acc += y0 * g_val[e] + y1 * g_val[e + 1] + y2 * g_val[e + 2] + y3 * g_val[e + 3];
        }
        for (; e < e1; e++) acc += y[g_col[e]] * g_val[e];
        out[i] = acc;
    }
    s1[t] = (i < n) ? acc : 0.f;
    s2[t] = (i < n) ? acc * acc : 0.f;
    __syncthreads();
    for (int o = 128; o; o >>= 1) {
        if (t < o) { s1[t] += s1[t + o]; s2[t] += s2[t + o]; }
        __syncthreads();
    }
    if (t == 0) {
        atomicAdd(&g_sum[0], (double)s1[0]);
        atomicAdd(&g_sq[0], (double)s2[0]);
    }
}

// bn∘inorm∘lnorm collapses to v*scale_c + beta_c (lnorm global mean is 0).
// Also resets g_sum/g_sq for the next layer's accumulation.
__global__ void k_consts(const float* __restrict__ g, const float* __restrict__ lw,
                         const float* __restrict__ lb, int C, int n) {
    __shared__ float red[128];
    int c = threadIdx.x;
    float alpha = 0.f, v = 0.f, m = 0.f;
    if (c < C) {
        double md = g_sum[c] / (double)n;
        double vd = g_sq[c] / (double)n - md * md;
        if (vd < 0.0) vd = 0.0;
        m = (float)md; v = (float)vd;
        float r1 = rsqrtf(v + EPSC);
        float gv = g[c];
        float var1 = gv * gv * v * r1 * r1;       // var of BN output
        alpha = gv * r1 * rsqrtf(var1 + EPSC);    // inorm(bn(.)) slope
        red[c] = alpha * alpha * v;               // contribution to lnorm var
    } else {
        red[c] = 0.f;
    }
    __syncthreads();
    for (int o = 64; o; o >>= 1) {
        if (c < o) red[c] += red[c + o];
        __syncthreads();
    }
    float v2 = red[0] / (float)C;
    if (c < C) {
        float s = alpha * rsqrtf(v2 + EPSC) * lw[c];
        g_scale[c] = s;
        g_beta[c] = lb[c] - m * s;
    }
    // reset stats for next layer (own slot only; read already done above)
    g_sum[c] = 0.0;
    g_sq[c] = 0.0;
}

__global__ void k_final(const float* __restrict__ gy, float* __restrict__ out, int n) {
    int i = blockIdx.x * blockDim.x + threadIdx.x;
    if (i < n) out[i] = fmaf(gy[i], g_scale[0], g_beta[0]);
}

// ------------------------------ launch --------------------------------------
extern "C" void kernel_launch(void* const* d_in, const int* in_sizes, int n_in,
                              void* d_out, int out_size) {
    const float* x  = (const float*)d_in[0];
    const void*  ei = d_in[1];
    const float* W1 = (const float*)d_in[2];
    const float* g1 = (const float*)d_in[4];
    const float* lw1 = (const float*)d_in[6];
    const float* lb1 = (const float*)d_in[7];
    const float* W2 = (const float*)d_in[8];
    const float* g2 = (const float*)d_in[10];
    const float* lw2 = (const float*)d_in[12];
    const float* lb2 = (const float*)d_in[13];
    const float* W3 = (const float*)d_in[14];
    const float* g3 = (const float*)d_in[16];
    const float* lw3 = (const float*)d_in[18];
    const float* lb3 = (const float*)d_in[19];

    int n = in_sizes[0] / DIN;   // 100000
    int E = in_sizes[1] / 2;     // 400000
    int nb1024 = (n + 1023) / 1024;

    const int SM1 = DIN * GR * 4 + DIN * DHD * 8;   // 16640 + 32768 = 49408
    const int SM2 = DHD * GR * 4 + 32 * DHD * 8;    // 66560 + 32768 = 99328
    cudaFuncSetAttribute(k_gemm1f, cudaFuncAttributeMaxDynamicSharedMemorySize, SM1);
    cudaFuncSetAttribute(k_gemm2f, cudaFuncAttributeMaxDynamicSharedMemorySize, SM2);

    float* Hb; float* Ab; float* yb; float* gyb;
    cudaGetSymbolAddress((void**)&Hb,  g_H);
    cudaGetSymbolAddress((void**)&Ab,  g_A);
    cudaGetSymbolAddress((void**)&yb,  g_y);
    cudaGetSymbolAddress((void**)&gyb, g_gy);

    int nblk = (n + 127) / 128;

    // ---- graph preprocessing (merged kernels) ----
    k_zero_init<<<(n + 255) / 256, 256>>>(ei, n);
    k_count<<<(E + 255) / 256, 256>>>(ei, E);
    k_scan_local<<<nb1024, 1024>>>(n, nb1024);     // also computes g_dinv
    k_scan_tops<<<1, 128>>>(nb1024);
    k_scan_final<<<(n + 255) / 256, 256>>>(n);
    k_fill<<<(E + 255) / 256, 256>>>(ei, E);

    // ---- layer 1: fused gather(x) + GEMM1 (+stats), consts (+stats reset) ----
    k_gemm1f<<<nblk, 256, SM1>>>(x, W1, Hb, n);
    k_consts<<<1, 128>>>(g1, lw1, lb1, DHD, n);

    // ---- layer 2: fused norm+relu+gather(h1) + GEMM2 (+stats), consts ----
    k_gemm2f<<<nblk, 256, SM2>>>(Hb, W2, Ab, n);
    k_consts<<<1, 128>>>(g2, lw2, lb2, DHD, n);

    // ---- layer 3: (norm(h2) @ W3) then scalar aggregation (+stats fused) ----
    k_gemv<<<(n + 7) / 8, 256>>>(Ab, W3, yb, n);
    k_gather1s<<<(n + 255) / 256, 256>>>(yb, gyb, n);
    k_consts<<<1, 128>>>(g3, lw3, lb3, 1, n);
    k_final<<<(n + 255) / 256, 256>>>(gyb, (float*)d_out, n);
}